// round 15
// baseline (speedup 1.0000x reference)
#include <cuda_runtime.h>
#include <cstdint>

// LIF forward scan (FINAL — practical DRAM roofline for this access mix):
//   v_t = BETA * v_{t-1} * (1 - s_{t-1}) + i_t   (hard reset)
//   s_t = (v_t >= 1.0)
// Outputs: spikes (B,T,H), membrane (B,T,H), v_final (B,H) — concatenated in d_out.
//
// Config (best of 12 measured variants, 61.0us kernel / 6.6 TB/s app-effective
// = 82% of HBM spec on a 1R:2W three-stream mix):
//  - 4 chains per thread (float4): 512B warp-level bursts on all three streams
//  - 6-stage cp.async smem ring for input (constant-depth read pipeline;
//    per-thread self-copy of its own 16B segment -> no block syncs needed)
//  - 8-step register-staged, stream-segregated output flush (longer
//    single-stream DRAM run lengths; measured +2.5pp DRAM busy)
//  - 64-thread blocks (2 warps -> distinct SMSPs), 128 blocks
// Measured-flat levers (not used): deeper pipelines, rolling prefetch,
// phase decorrelation, L2 policy hints, >8-step run lengths, 148-SM spread.

#define LIF_BETA 0.904837f

static constexpr int Bc = 16;
static constexpr int Tc = 1024;
static constexpr int Hc = 2048;
static constexpr int CPT = 4;                 // chains per thread
static constexpr int NT  = 64;                // threads per block (2 warps)
static constexpr int BH  = NT * CPT;          // 256 h per block
static constexpr int CHUNK  = 8;              // time steps per stage / flush batch
static constexpr int NSTAGE = 6;              // ring depth (48KB smem)
static constexpr int NCHUNK = Tc / CHUNK;     // 128

__device__ __forceinline__ void cp_async16(uint32_t saddr, const void* gsrc) {
    asm volatile("cp.async.cg.shared.global [%0], [%1], 16;\n"
                 :: "r"(saddr), "l"(gsrc));
}
__device__ __forceinline__ void cp_commit() {
    asm volatile("cp.async.commit_group;\n");
}
template <int N>
__device__ __forceinline__ void cp_wait() {
    asm volatile("cp.async.wait_group %0;\n" :: "n"(N));
}

__global__ __launch_bounds__(NT)
void lif_kernel(const float* __restrict__ in,   // (B, T, H)
                const float* __restrict__ v0,   // (B, H)
                float* __restrict__ out)        // [spikes | membrane | v_final]
{
    __shared__ float stage[NSTAGE][CHUNK][BH];  // 6*8*256*4 = 48KB

    const int tid = threadIdx.x;
    const int chain0 = blockIdx.x * BH + tid * CPT;
    const int b  = chain0 >> 11;                      // / 2048 (blocks never straddle b)
    const int h0 = (blockIdx.x * BH) & (Hc - 1);

    const size_t plane = (size_t)Bc * Tc * Hc;
    float* __restrict__ spikes = out;
    float* __restrict__ mem    = out + plane;
    float* __restrict__ vfin   = out + 2 * plane;

    const size_t rowbase = (size_t)b * Tc * Hc + h0;
    const int elem = tid * CPT;                       // this thread's float4 slot

    // Thread copies and later consumes exactly its own 16B segment of each
    // row -> per-thread cp.async wait_group ordering suffices, no block syncs.
    auto issue_stage = [&](int c) {
        const int st = c % NSTAGE;
        const size_t gbase = rowbase + (size_t)c * CHUNK * Hc + elem;
#pragma unroll
        for (int e = 0; e < CHUNK; ++e) {
            uint32_t saddr = (uint32_t)__cvta_generic_to_shared(&stage[st][e][elem]);
            cp_async16(saddr, in + gbase + (size_t)e * Hc);
        }
    };

#pragma unroll
    for (int c = 0; c < NSTAGE - 1; ++c) {
        issue_stage(c);
        cp_commit();
    }

    float4 vi = *(const float4*)(v0 + chain0);
    float va = vi.x, vb = vi.y, vc = vi.z, vd = vi.w;
    float sa = 0.f, sb = 0.f, sc = 0.f, sd = 0.f;

    float4 spb[CHUNK];   // staged spike rows (compile-time indexed only!)
    float4 vmb[CHUNK];   // staged membrane rows

    for (int c = 0; c < NCHUNK; ++c) {
        if (c + NSTAGE - 1 < NCHUNK)
            issue_stage(c + NSTAGE - 1);
        cp_commit();
        cp_wait<NSTAGE - 1>();

        const int st = c % NSTAGE;

        // Phase 1: compute CHUNK steps, outputs staged in registers.
#pragma unroll
        for (int e = 0; e < CHUNK; ++e) {
            const float4 x = *(const float4*)&stage[st][e][elem];
            float vr;
            vr = (sa != 0.f) ? 0.f : va;  va = fmaf(LIF_BETA, vr, x.x);  sa = (va >= 1.f) ? 1.f : 0.f;
            vr = (sb != 0.f) ? 0.f : vb;  vb = fmaf(LIF_BETA, vr, x.y);  sb = (vb >= 1.f) ? 1.f : 0.f;
            vr = (sc != 0.f) ? 0.f : vc;  vc = fmaf(LIF_BETA, vr, x.z);  sc = (vc >= 1.f) ? 1.f : 0.f;
            vr = (sd != 0.f) ? 0.f : vd;  vd = fmaf(LIF_BETA, vr, x.w);  sd = (vd >= 1.f) ? 1.f : 0.f;
            spb[e] = make_float4(sa, sb, sc, sd);
            vmb[e] = make_float4(va, vb, vc, vd);
        }

        const size_t obase = rowbase + (size_t)c * CHUNK * Hc + elem;

        // Phase 2: flush spike stream as one burst (CHUNK x 1KB/block).
#pragma unroll
        for (int e = 0; e < CHUNK; ++e)
            __stcs((float4*)(spikes + obase + (size_t)e * Hc), spb[e]);

        // Phase 3: flush membrane stream as one burst.
#pragma unroll
        for (int e = 0; e < CHUNK; ++e)
            __stcs((float4*)(mem + obase + (size_t)e * Hc), vmb[e]);
    }

    *(float4*)(vfin + chain0) = make_float4(va, vb, vc, vd);
}

extern "C" void kernel_launch(void* const* d_in, const int* in_sizes, int n_in,
                              void* d_out, int out_size)
{
    const float* input = (const float*)d_in[0];   // (16, 1024, 2048) float32
    const float* v0    = (const float*)d_in[1];   // (16, 2048) float32
    float* out         = (float*)d_out;

    const int nchains = Bc * Hc;                  // 32768
    const int grid = nchains / BH;                // 128 blocks of 2 warps
    lif_kernel<<<grid, NT>>>(input, v0, out);
}

// round 16
// speedup vs baseline: 1.0974x; 1.0974x over previous
#include <cuda_runtime.h>
#include <cstdint>

// LIF forward scan (re-bench of best config — R15 anomaly check):
//   v_t = BETA * v_{t-1} * (1 - s_{t-1}) + i_t   (hard reset)
//   s_t = (v_t >= 1.0)
// Outputs: spikes (B,T,H), membrane (B,T,H), v_final (B,H) — concatenated in d_out.
//
// Identical to the R9/R14 kernel (61.0us kernel best). R15 ran the same source
// 10us slower with a shifted profile (L1 66%, issue 34%) — consistent with a
// clock/DVFS or container anomaly, not a code property. Re-benching unchanged
// to confirm before any further conclusion.

#define LIF_BETA 0.904837f

static constexpr int Bc = 16;
static constexpr int Tc = 1024;
static constexpr int Hc = 2048;
static constexpr int CPT = 4;                 // chains per thread
static constexpr int NT  = 64;                // threads per block (2 warps)
static constexpr int BH  = NT * CPT;          // 256 h per block
static constexpr int CHUNK  = 8;              // time steps per stage / flush batch
static constexpr int NSTAGE = 6;              // ring depth (48KB smem)
static constexpr int NCHUNK = Tc / CHUNK;     // 128

__device__ __forceinline__ void cp_async16(uint32_t saddr, const void* gsrc) {
    asm volatile("cp.async.cg.shared.global [%0], [%1], 16;\n"
                 :: "r"(saddr), "l"(gsrc));
}
__device__ __forceinline__ void cp_commit() {
    asm volatile("cp.async.commit_group;\n");
}
template <int N>
__device__ __forceinline__ void cp_wait() {
    asm volatile("cp.async.wait_group %0;\n" :: "n"(N));
}

__global__ __launch_bounds__(NT)
void lif_kernel(const float* __restrict__ in,   // (B, T, H)
                const float* __restrict__ v0,   // (B, H)
                float* __restrict__ out)        // [spikes | membrane | v_final]
{
    __shared__ float stage[NSTAGE][CHUNK][BH];  // 6*8*256*4 = 48KB

    const int tid = threadIdx.x;
    const int chain0 = blockIdx.x * BH + tid * CPT;
    const int b  = chain0 >> 11;                      // / 2048
    const int h0 = (blockIdx.x * BH) & (Hc - 1);

    const size_t plane = (size_t)Bc * Tc * Hc;
    float* __restrict__ spikes = out;
    float* __restrict__ mem    = out + plane;
    float* __restrict__ vfin   = out + 2 * plane;

    const size_t rowbase = (size_t)b * Tc * Hc + h0;
    const int elem = tid * CPT;                       // this thread's float4 slot

    // Thread copies and later consumes exactly its own 16B segment of each
    // row -> per-thread cp.async wait_group ordering suffices, no block syncs.
    auto issue_stage = [&](int c) {
        const int st = c % NSTAGE;
        const size_t gbase = rowbase + (size_t)c * CHUNK * Hc + elem;
#pragma unroll
        for (int e = 0; e < CHUNK; ++e) {
            uint32_t saddr = (uint32_t)__cvta_generic_to_shared(&stage[st][e][elem]);
            cp_async16(saddr, in + gbase + (size_t)e * Hc);
        }
    };

#pragma unroll
    for (int c = 0; c < NSTAGE - 1; ++c) {
        issue_stage(c);
        cp_commit();
    }

    float4 vi = *(const float4*)(v0 + chain0);
    float va = vi.x, vb = vi.y, vc = vi.z, vd = vi.w;
    float sa = 0.f, sb = 0.f, sc = 0.f, sd = 0.f;

    float4 spb[CHUNK];   // staged spike rows (compile-time indexed only!)
    float4 vmb[CHUNK];   // staged membrane rows

    for (int c = 0; c < NCHUNK; ++c) {
        if (c + NSTAGE - 1 < NCHUNK)
            issue_stage(c + NSTAGE - 1);
        cp_commit();
        cp_wait<NSTAGE - 1>();

        const int st = c % NSTAGE;

        // Phase 1: compute CHUNK steps, outputs staged in registers.
#pragma unroll
        for (int e = 0; e < CHUNK; ++e) {
            const float4 x = *(const float4*)&stage[st][e][elem];
            float vr;
            vr = (sa != 0.f) ? 0.f : va;  va = fmaf(LIF_BETA, vr, x.x);  sa = (va >= 1.f) ? 1.f : 0.f;
            vr = (sb != 0.f) ? 0.f : vb;  vb = fmaf(LIF_BETA, vr, x.y);  sb = (vb >= 1.f) ? 1.f : 0.f;
            vr = (sc != 0.f) ? 0.f : vc;  vc = fmaf(LIF_BETA, vr, x.z);  sc = (vc >= 1.f) ? 1.f : 0.f;
            vr = (sd != 0.f) ? 0.f : vd;  vd = fmaf(LIF_BETA, vr, x.w);  sd = (vd >= 1.f) ? 1.f : 0.f;
            spb[e] = make_float4(sa, sb, sc, sd);
            vmb[e] = make_float4(va, vb, vc, vd);
        }

        const size_t obase = rowbase + (size_t)c * CHUNK * Hc + elem;

        // Phase 2: flush spike stream as one burst (CHUNK x 1KB/block).
#pragma unroll
        for (int e = 0; e < CHUNK; ++e)
            __stcs((float4*)(spikes + obase + (size_t)e * Hc), spb[e]);

        // Phase 3: flush membrane stream as one burst.
#pragma unroll
        for (int e = 0; e < CHUNK; ++e)
            __stcs((float4*)(mem + obase + (size_t)e * Hc), vmb[e]);
    }

    *(float4*)(vfin + chain0) = make_float4(va, vb, vc, vd);
}

extern "C" void kernel_launch(void* const* d_in, const int* in_sizes, int n_in,
                              void* d_out, int out_size)
{
    const float* input = (const float*)d_in[0];   // (16, 1024, 2048) float32
    const float* v0    = (const float*)d_in[1];   // (16, 2048) float32
    float* out         = (float*)d_out;

    const int nchains = Bc * Hc;                  // 32768
    const int grid = nchains / BH;                // 128 blocks of 2 warps
    lif_kernel<<<grid, NT>>>(input, v0, out);
}